// round 1
// baseline (speedup 1.0000x reference)
#include <cuda_runtime.h>

#define T_TOK 8192
#define HD    1024
#define NE    8

#define TM 128
#define TN 128
#define TK 8
#define LROW (TM + 4)   // padded smem row: conflict-free transposed stores

// ---- scratch (device globals; no allocations allowed) ----
__device__ int   g_counts[NE];
__device__ int   g_tok[NE * T_TOK];
__device__ float g_wt [NE * T_TOK];

// ---------------------------------------------------------------------------
// Kernel 0: zero output + counters (output buffer is poisoned each run)
// ---------------------------------------------------------------------------
__global__ void k_init(float* __restrict__ out) {
    int i = blockIdx.x * blockDim.x + threadIdx.x;
    if (i < T_TOK * HD) out[i] = 0.0f;
    if (i < NE) g_counts[i] = 0;
}

// ---------------------------------------------------------------------------
// Kernel 1: router. One warp per token. Top-2 of scores == top-2 of softmax;
// renormalized weights reduce to a single sigmoid of the score gap.
// ---------------------------------------------------------------------------
__global__ void k_router(const float* __restrict__ x,
                         const float* __restrict__ rw,
                         const float* __restrict__ rb) {
    __shared__ float s_rw[NE * HD];
    __shared__ float s_rb[NE];
    int tid = threadIdx.x;
    for (int i = tid; i < NE * HD; i += blockDim.x) s_rw[i] = rw[i];
    if (tid < NE) s_rb[tid] = rb[tid];
    __syncthreads();

    int warp = tid >> 5, lane = tid & 31;
    int t = blockIdx.x * 8 + warp;                 // blockDim=256 -> 8 tokens
    const float* xr = x + (size_t)t * HD;

    float xv[32];
#pragma unroll
    for (int i = 0; i < 32; i++) xv[i] = xr[lane + 32 * i];

    float sc[NE];
#pragma unroll
    for (int e = 0; e < NE; e++) {
        float s = 0.0f;
        const float* wr = s_rw + e * HD;
#pragma unroll
        for (int i = 0; i < 32; i++) s += xv[i] * wr[lane + 32 * i];
#pragma unroll
        for (int o = 16; o > 0; o >>= 1) s += __shfl_xor_sync(0xffffffffu, s, o);
        sc[e] = s + s_rb[e];
    }

    if (lane == 0) {
        int e0 = 0;
#pragma unroll
        for (int e = 1; e < NE; e++) if (sc[e] > sc[e0]) e0 = e;
        int e1 = (e0 == 0) ? 1 : 0;
#pragma unroll
        for (int e = 0; e < NE; e++) if (e != e1 && e != e0 && sc[e] > sc[e1]) e1 = e;

        float d  = __expf(sc[e1] - sc[e0]);        // <= 1, stable
        float w0 = 1.0f / (1.0f + d);
        float w1 = 1.0f - w0;

        int p0 = atomicAdd(&g_counts[e0], 1);
        g_tok[e0 * T_TOK + p0] = t;  g_wt[e0 * T_TOK + p0] = w0;
        int p1 = atomicAdd(&g_counts[e1], 1);
        g_tok[e1 * T_TOK + p1] = t;  g_wt[e1 * T_TOK + p1] = w1;
    }
}

// ---------------------------------------------------------------------------
// Kernel 2: grouped GEMM per expert. 128x128x8 tiles, double-buffered smem,
// 8x8 microtile/thread, epilogue scatter: out[t, n] += w * (acc + bias[n]).
// ---------------------------------------------------------------------------
__global__ void __launch_bounds__(256, 2)
k_moe_gemm(const float* __restrict__ x,
           const float* __restrict__ ew,
           const float* __restrict__ eb,
           float* __restrict__ out) {
    int e   = blockIdx.z;
    int cnt = g_counts[e];
    int m0  = blockIdx.y * TM;
    if (m0 >= cnt) return;
    int n0  = blockIdx.x * TN;

    __shared__ float Xs[2][TK][LROW];
    __shared__ float Ws[2][TK][LROW];
    __shared__ int   s_tok[TM];
    __shared__ float s_w[TM];

    int tid = threadIdx.x;
    if (tid < TM) {
        int m = m0 + tid;
        if (m < cnt) { s_tok[tid] = g_tok[e * T_TOK + m]; s_w[tid] = g_wt[e * T_TOK + m]; }
        else         { s_tok[tid] = 0;                    s_w[tid] = 0.0f; }
    }
    __syncthreads();

    // loader mapping: each thread owns one float4 of X and one of W per k-tile
    int lm = tid >> 1;            // row within tile, 0..127
    int lk = (tid & 1) * 4;       // 0 or 4
    const float* xptr = x  + (size_t)s_tok[lm] * HD + lk;
    const float* wptr = ew + (size_t)e * HD * HD + (size_t)(n0 + lm) * HD + lk;

    // compute mapping
    int tx = tid & 15, ty = tid >> 4;

    float acc[8][8];
#pragma unroll
    for (int i = 0; i < 8; i++)
#pragma unroll
        for (int j = 0; j < 8; j++) acc[i][j] = 0.0f;

    // prologue: tile 0 -> buf 0
    float4 xa = *(const float4*)(xptr);
    float4 wa = *(const float4*)(wptr);
    {
        const float* xf = (const float*)&xa;
        const float* wf = (const float*)&wa;
#pragma unroll
        for (int j = 0; j < 4; j++) { Xs[0][lk + j][lm] = xf[j]; Ws[0][lk + j][lm] = wf[j]; }
    }
    __syncthreads();

    const int NK = HD / TK;       // 128
    for (int kt = 0; kt < NK; kt++) {
        int cur = kt & 1;
        if (kt + 1 < NK) {
            xa = *(const float4*)(xptr + (kt + 1) * TK);
            wa = *(const float4*)(wptr + (kt + 1) * TK);
        }
#pragma unroll
        for (int k = 0; k < TK; k++) {
            float4 a0 = *(const float4*)&Xs[cur][k][ty * 4];
            float4 a1 = *(const float4*)&Xs[cur][k][ty * 4 + 64];
            float4 b0 = *(const float4*)&Ws[cur][k][tx * 4];
            float4 b1 = *(const float4*)&Ws[cur][k][tx * 4 + 64];
            float a[8] = {a0.x, a0.y, a0.z, a0.w, a1.x, a1.y, a1.z, a1.w};
            float b[8] = {b0.x, b0.y, b0.z, b0.w, b1.x, b1.y, b1.z, b1.w};
#pragma unroll
            for (int i = 0; i < 8; i++)
#pragma unroll
                for (int j = 0; j < 8; j++) acc[i][j] += a[i] * b[j];
        }
        if (kt + 1 < NK) {
            int nxt = cur ^ 1;
            const float* xf = (const float*)&xa;
            const float* wf = (const float*)&wa;
#pragma unroll
            for (int j = 0; j < 4; j++) { Xs[nxt][lk + j][lm] = xf[j]; Ws[nxt][lk + j][lm] = wf[j]; }
            __syncthreads();
        }
    }

    // epilogue: out[t, n0+n] += w * (acc + bias)
    const float* brow = eb + (size_t)e * HD + n0;
#pragma unroll
    for (int i = 0; i < 8; i++) {
        int m = (i < 4) ? (ty * 4 + i) : (64 + ty * 4 + (i - 4));
        if (m0 + m < cnt) {
            int   t = s_tok[m];
            float w = s_w[m];
            float* orow = out + (size_t)t * HD + n0;
#pragma unroll
            for (int j = 0; j < 8; j++) {
                int n = (j < 4) ? (tx * 4 + j) : (64 + tx * 4 + (j - 4));
                atomicAdd(&orow[n], w * (acc[i][j] + brow[n]));
            }
        }
    }
}

// ---------------------------------------------------------------------------
extern "C" void kernel_launch(void* const* d_in, const int* in_sizes, int n_in,
                              void* d_out, int out_size) {
    const float* x  = (const float*)d_in[0];
    const float* rw = (const float*)d_in[1];
    const float* rb = (const float*)d_in[2];
    const float* ew = (const float*)d_in[3];
    const float* eb = (const float*)d_in[4];
    float* out = (float*)d_out;

    k_init<<<(T_TOK * HD + 255) / 256, 256>>>(out);
    k_router<<<T_TOK / 8, 256>>>(x, rw, rb);
    dim3 grid(HD / TN, T_TOK / TM, NE);
    k_moe_gemm<<<grid, 256>>>(x, ew, eb, out);
}

// round 3
// speedup vs baseline: 6.5695x; 6.5695x over previous
#include <cuda_runtime.h>
#include <cuda_fp16.h>
#include <cstdint>

#define TT 8192
#define HD 1024
#define NE 8
#define NK 32          // 1024 / BK
#define BK 32

// ---- scratch (device globals; no allocations allowed) ----------------------
__device__ int    g_counts[NE];
__device__ int    g_tok[NE * TT];          // slot -> token*2 + choice (-1 pad)
__device__ float  g_tws[2 * TT];           // (token,choice) -> combine weight
__device__ __half g_xh[(size_t)TT * HD];
__device__ __half g_wh[(size_t)NE * HD * HD];
__device__ float  g_part[(size_t)2 * TT * HD];

// ---- PTX helpers (baseline compute_103-safe: sm_80-era ops only) -----------
__device__ __forceinline__ uint32_t smem_u32(const void* p) {
    uint32_t a;
    asm("{ .reg .u64 t; cvta.to.shared.u64 t, %1; cvt.u32.u64 %0, t; }"
        : "=r"(a) : "l"(p));
    return a;
}
#define CP16(dst, src) \
    asm volatile("cp.async.cg.shared.global [%0], [%1], 16;" :: "r"(dst), "l"(src))
#define CP_COMMIT() asm volatile("cp.async.commit_group;" ::: "memory")
#define CP_WAIT2()  asm volatile("cp.async.wait_group 2;" ::: "memory")

__device__ __forceinline__ void ldsm4(uint32_t* r, uint32_t a) {
    asm volatile("ldmatrix.sync.aligned.m8n8.x4.shared.b16 {%0,%1,%2,%3}, [%4];"
                 : "=r"(r[0]), "=r"(r[1]), "=r"(r[2]), "=r"(r[3]) : "r"(a));
}
__device__ __forceinline__ void ldsm2(uint32_t* r, uint32_t a) {
    asm volatile("ldmatrix.sync.aligned.m8n8.x2.shared.b16 {%0,%1}, [%2];"
                 : "=r"(r[0]), "=r"(r[1]) : "r"(a));
}
__device__ __forceinline__ void mma16816(float* c, const uint32_t* a, const uint32_t* b) {
    asm volatile(
        "mma.sync.aligned.m16n8k16.row.col.f32.f16.f16.f32 "
        "{%0,%1,%2,%3}, {%4,%5,%6,%7}, {%8,%9}, {%0,%1,%2,%3};"
        : "+f"(c[0]), "+f"(c[1]), "+f"(c[2]), "+f"(c[3])
        : "r"(a[0]), "r"(a[1]), "r"(a[2]), "r"(a[3]), "r"(b[0]), "r"(b[1]));
}

// swizzled 16B-chunk offset within a 128x32-fp16 tile (64B rows)
__device__ __forceinline__ uint32_t swz(int row, int chunk) {
    return (uint32_t)(row * 64 + ((chunk ^ ((row >> 1) & 3)) << 4));
}

// ---------------------------------------------------------------------------
__global__ void k_init() {
    if (threadIdx.x < NE) g_counts[threadIdx.x] = 0;
}

// Router + fp16 cast of x. One warp per token.
__global__ void k_router(const float* __restrict__ x,
                         const float* __restrict__ rw,
                         const float* __restrict__ rb) {
    __shared__ float s_rw[NE * HD];
    __shared__ float s_rb[NE];
    int tid = threadIdx.x;
    for (int i = tid; i < NE * HD; i += blockDim.x) s_rw[i] = rw[i];
    if (tid < NE) s_rb[tid] = rb[tid];
    __syncthreads();

    int warp = tid >> 5, lane = tid & 31;
    int t = blockIdx.x * 8 + warp;
    const float* xr = x + (size_t)t * HD;

    float xv[32];
#pragma unroll
    for (int i = 0; i < 32; i++) xv[i] = xr[lane + 32 * i];

    __half* xh = g_xh + (size_t)t * HD;
#pragma unroll
    for (int i = 0; i < 32; i++) xh[lane + 32 * i] = __float2half_rn(xv[i]);

    float sc[NE];
#pragma unroll
    for (int e = 0; e < NE; e++) {
        float s = 0.0f;
        const float* wr = s_rw + e * HD;
#pragma unroll
        for (int i = 0; i < 32; i++) s += xv[i] * wr[lane + 32 * i];
#pragma unroll
        for (int o = 16; o > 0; o >>= 1) s += __shfl_xor_sync(0xffffffffu, s, o);
        sc[e] = s + s_rb[e];
    }

    if (lane == 0) {
        int e0 = 0;
#pragma unroll
        for (int e = 1; e < NE; e++) if (sc[e] > sc[e0]) e0 = e;
        int e1 = (e0 == 0) ? 1 : 0;
#pragma unroll
        for (int e = 0; e < NE; e++) if (e != e1 && e != e0 && sc[e] > sc[e1]) e1 = e;

        float d  = __expf(sc[e1] - sc[e0]);   // <= 1, stable
        float w0 = 1.0f / (1.0f + d);
        g_tws[2 * t]     = w0;
        g_tws[2 * t + 1] = 1.0f - w0;
        int p0 = atomicAdd(&g_counts[e0], 1);
        g_tok[e0 * TT + p0] = t * 2;
        int p1 = atomicAdd(&g_counts[e1], 1);
        g_tok[e1 * TT + p1] = t * 2 + 1;
    }
}

// expert_w fp32 -> fp16
__global__ void k_convw(const float* __restrict__ w) {
    size_t i = ((size_t)blockIdx.x * blockDim.x + threadIdx.x) * 4;
    float4 v = *(const float4*)(w + i);
    __half2* p = (__half2*)(g_wh + i);
    p[0] = __floats2half2_rn(v.x, v.y);
    p[1] = __floats2half2_rn(v.z, v.w);
}

// ---------------------------------------------------------------------------
// Grouped GEMM: 128x128 tile per CTA, fp16 HMMA, 3-stage cp.async pipeline.
// Output: g_part[(token,choice)] row = x_tok . W_e^T + b_e   (no weights yet)
// ---------------------------------------------------------------------------
__global__ void __launch_bounds__(256)
k_gemm(const float* __restrict__ eb) {
    int e   = blockIdx.z;
    int cnt = g_counts[e];
    int m0  = blockIdx.y * 128;
    if (m0 >= cnt) return;
    int n0  = blockIdx.x * 128;

    __shared__ int   s_tok[128];
    __shared__ float s_bias[128];
    extern __shared__ __align__(128) char dsm[];   // 3 stages x (A 8KB + B 8KB)

    int tid = threadIdx.x, lane = tid & 31, wid = tid >> 5;

    if (tid < 128) {
        int m = m0 + tid;
        s_tok[tid]  = (m < cnt) ? g_tok[e * TT + m] : -1;
        s_bias[tid] = eb[e * HD + n0 + tid];
    }
    __syncthreads();

    // loader mapping: thread -> (row, 2 chunks)
    int lr = tid >> 1;
    int lc = (tid & 1) * 2;
    int v  = s_tok[lr];
    int tok = (v < 0 ? 0 : v) >> 1;
    const char* ga = (const char*)(g_xh + (size_t)tok * HD + lc * 8);
    const char* gb = (const char*)(g_wh + (size_t)e * HD * HD
                                        + (size_t)(n0 + lr) * HD + lc * 8);
    uint32_t sa0 = swz(lr, lc), sa1 = swz(lr, lc + 1);
    uint32_t sbase = smem_u32(dsm);

    auto issue = [&](int kt) {
        uint32_t ab = sbase + (uint32_t)(kt % 3) * 16384u;
        uint32_t bb = ab + 8192u;
        const char* a = ga + kt * (BK * 2);
        const char* b = gb + kt * (BK * 2);
        CP16(ab + sa0, a);
        CP16(ab + sa1, a + 16);
        CP16(bb + sa0, b);
        CP16(bb + sa1, b + 16);
    };

    // mma fragment smem offsets (within stage A/B base)
    int wm = (wid >> 2) * 64, wn = (wid & 3) * 32;
    uint32_t aoff[4][2], boff[4][2];
#pragma unroll
    for (int mt = 0; mt < 4; mt++)
#pragma unroll
        for (int ks = 0; ks < 2; ks++)
            aoff[mt][ks] = swz(wm + mt * 16 + (lane & 15), ks * 2 + (lane >> 4));
#pragma unroll
    for (int nt = 0; nt < 4; nt++)
#pragma unroll
        for (int ks = 0; ks < 2; ks++)
            boff[nt][ks] = swz(wn + nt * 8 + (lane & 7), ks * 2 + ((lane >> 3) & 1));

    float acc[4][4][4];
#pragma unroll
    for (int mt = 0; mt < 4; mt++)
#pragma unroll
        for (int nt = 0; nt < 4; nt++)
#pragma unroll
            for (int j = 0; j < 4; j++) acc[mt][nt][j] = 0.0f;

    issue(0); CP_COMMIT();
    issue(1); CP_COMMIT();

    for (int kt = 0; kt < NK; kt++) {
        if (kt + 2 < NK) issue(kt + 2);
        CP_COMMIT();
        CP_WAIT2();
        __syncthreads();

        uint32_t ab = sbase + (uint32_t)(kt % 3) * 16384u;
        uint32_t bb = ab + 8192u;
#pragma unroll
        for (int ks = 0; ks < 2; ks++) {
            uint32_t ar[4][4], br[4][2];
#pragma unroll
            for (int mt = 0; mt < 4; mt++) ldsm4(ar[mt], ab + aoff[mt][ks]);
#pragma unroll
            for (int nt = 0; nt < 4; nt++) ldsm2(br[nt], bb + boff[nt][ks]);
#pragma unroll
            for (int mt = 0; mt < 4; mt++)
#pragma unroll
                for (int nt = 0; nt < 4; nt++)
                    mma16816(acc[mt][nt], ar[mt], br[nt]);
        }
        __syncthreads();
    }

    // epilogue: + bias, store partial rows (combine weights applied later)
#pragma unroll
    for (int mt = 0; mt < 4; mt++) {
#pragma unroll
        for (int h = 0; h < 2; h++) {
            int row = wm + mt * 16 + (lane >> 2) + h * 8;
            int vv  = s_tok[row];
            if (vv >= 0) {
                float* prow = g_part + (size_t)vv * HD + n0;
#pragma unroll
                for (int nt = 0; nt < 4; nt++) {
                    int c = wn + nt * 8 + (lane & 3) * 2;
                    float2 o;
                    o.x = acc[mt][nt][2 * h]     + s_bias[c];
                    o.y = acc[mt][nt][2 * h + 1] + s_bias[c + 1];
                    *(float2*)(prow + c) = o;
                }
            }
        }
    }
}

// out[t] = w0 * part[2t] + w1 * part[2t+1]
__global__ void k_combine(float* __restrict__ out) {
    int t = blockIdx.x, tid = threadIdx.x;
    float w0 = g_tws[2 * t], w1 = g_tws[2 * t + 1];
    const float4* p0 = (const float4*)(g_part + (size_t)(2 * t) * HD);
    const float4* p1 = (const float4*)(g_part + (size_t)(2 * t + 1) * HD);
    float4 a = p0[tid], b = p1[tid];
    float4 o;
    o.x = w0 * a.x + w1 * b.x;
    o.y = w0 * a.y + w1 * b.y;
    o.z = w0 * a.z + w1 * b.z;
    o.w = w0 * a.w + w1 * b.w;
    ((float4*)(out + (size_t)t * HD))[tid] = o;
}

// ---------------------------------------------------------------------------
extern "C" void kernel_launch(void* const* d_in, const int* in_sizes, int n_in,
                              void* d_out, int out_size) {
    const float* x  = (const float*)d_in[0];
    const float* rw = (const float*)d_in[1];
    const float* rb = (const float*)d_in[2];
    const float* ew = (const float*)d_in[3];
    const float* eb = (const float*)d_in[4];
    float* out = (float*)d_out;

    const int DSM = 49152;    // 3 stages x 16KB
    static int done = 0;
    if (!done) {
        cudaFuncSetAttribute(k_gemm, cudaFuncAttributeMaxDynamicSharedMemorySize, DSM);
        done = 1;
    }

    k_init<<<1, 32>>>();
    k_router<<<TT / 8, 256>>>(x, rw, rb);
    k_convw<<<(NE * HD * HD) / 1024, 256>>>(ew);
    dim3 grid(HD / 128, 64, NE);
    k_gemm<<<grid, 256, DSM>>>(eb);
    k_combine<<<TT, 256>>>(out);
}